// round 1
// baseline (speedup 1.0000x reference)
#include <cuda_runtime.h>

// HiPoNet collapse: P = 0.5*(Wm/colsum) + 0.5*I is column-stochastic
// (every column of Wn sums to 1 by construction, diagonal of Wm is exp(0)=1
//  so colsums are >= 1 and finite). Therefore 1^T P^t = 1^T for all t, and
//  the node-mean of every diffusion feature P^t X equals the node-mean of X.
// Output: out[b, w*160 + k*32 + d] = mean_n(pc[b,n,d]) * alphas[w,d], k=0..4.

#define NPTS   2048
#define DIM    32
#define NW     4
#define NCOLL  5            // [X, PX, P^2X, P^4X, P^8X]
#define FOUT   (NW * NCOLL * DIM)   // 640 per batch

__global__ void hiponet_mean_kernel(const float* __restrict__ pc,
                                    const float* __restrict__ alphas,
                                    float* __restrict__ out)
{
    const int b  = blockIdx.x;       // 0..3
    const int t  = threadIdx.x;      // 0..1023
    const int dd = t & 31;           // feature dim
    const int ng = t >> 5;           // n-chunk lane, 0..31

    const float* __restrict__ base = pc + (size_t)b * NPTS * DIM;

    // Each thread sums 64 rows (n = ng + 32k), coalesced across dd.
    float s = 0.0f;
    #pragma unroll 8
    for (int k = 0; k < NPTS / 32; ++k) {
        s += base[(ng + (k << 5)) * DIM + dd];
    }

    __shared__ float sm[32][33];     // padded: no bank conflicts
    sm[ng][dd] = s;
    __syncthreads();

    #pragma unroll
    for (int stride = 16; stride > 0; stride >>= 1) {
        if (ng < stride) sm[ng][dd] += sm[ng + stride][dd];
        __syncthreads();
    }

    // sm[0][d] = sum_n pc[b,n,d]. Write 640 outputs for this batch.
    if (t < FOUT) {
        const int w  = t / (NCOLL * DIM);        // 0..3
        const int d2 = t & 31;                   // feature dim within 32-block
        const float mean = sm[0][d2] * (1.0f / (float)NPTS);
        out[b * FOUT + t] = mean * alphas[w * DIM + d2];
    }
}

extern "C" void kernel_launch(void* const* d_in, const int* in_sizes, int n_in,
                              void* d_out, int out_size)
{
    const float* pc     = (const float*)d_in[0];  // [4, 2048, 32] fp32
    // d_in[1] = sigma (unused: output is invariant to the diffusion operator)
    const float* alphas = (const float*)d_in[2];  // [4, 32] fp32
    float* out = (float*)d_out;                   // [4, 640] fp32

    hiponet_mean_kernel<<<4, 1024>>>(pc, alphas, out);
}

// round 2
// speedup vs baseline: 1.2000x; 1.2000x over previous
#include <cuda_runtime.h>

// HiPoNet collapse: P = 0.5*(Wm/colsum) + 0.5*I is column-stochastic, so
// 1^T P^t = 1^T and mean_n(P^t X) = mean_n(X) exactly. Output:
//   out[b, w*160 + k*32 + d] = mean_n(pc[b,n,d]) * alphas[w,d], k=0..4.
//
// R2: single-launch two-phase reduction. 128 blocks each sum a 64-row chunk
// with float4 (LDG.128) loads; last-arriving block reduces the 4 KB of
// partials and writes all 2560 outputs. Counter self-resets -> deterministic
// and graph-replayable.

#define NPTS   2048
#define DIM    32
#define NW     4
#define NCOLL  5
#define FOUT   (NW * NCOLL * DIM)        // 640 per batch
#define CHUNKS 32                        // chunks per batch
#define ROWS   (NPTS / CHUNKS)           // 64 rows per chunk
#define GRID   (4 * CHUNKS)              // 128 blocks
#define QPR    (DIM / 4)                 // 8 float4 per row

__device__ float        g_part[4][CHUNKS][DIM];  // partial column sums
__device__ unsigned int g_done;                   // zero-init; self-resetting

__global__ void hiponet_kernel(const float* __restrict__ pc,
                               const float* __restrict__ alphas,
                               float* __restrict__ out)
{
    const int b = blockIdx.x >> 5;       // batch 0..3
    const int c = blockIdx.x & 31;       // chunk 0..31
    const int t = threadIdx.x;           // 0..255
    const int q  = t & (QPR - 1);        // float4 slot within row, 0..7
    const int rg = t >> 3;               // row group, 0..31

    // ---- phase 1: sum 64 rows of this chunk (float4-vectorized) ----
    const float4* __restrict__ base =
        (const float4*)(pc + ((size_t)b * NPTS + (size_t)c * ROWS) * DIM);

    float4 a0 = base[(size_t)rg * QPR + q];           // rows rg
    float4 a1 = base[(size_t)(rg + 32) * QPR + q];    // rows rg+32
    float4 s = make_float4(a0.x + a1.x, a0.y + a1.y, a0.z + a1.z, a0.w + a1.w);

    __shared__ float4 sm[32][QPR];
    sm[rg][q] = s;
    __syncthreads();

    #pragma unroll
    for (int st = 16; st > 0; st >>= 1) {
        if (rg < st) {
            float4 o = sm[rg + st][q];
            float4 m = sm[rg][q];
            sm[rg][q] = make_float4(m.x + o.x, m.y + o.y, m.z + o.z, m.w + o.w);
        }
        __syncthreads();
    }

    if (t < QPR) {
        ((float4*)g_part[b][c])[t] = sm[0][t];
    }
    __threadfence();

    // ---- arrival count; last block finishes the job ----
    __shared__ bool is_last;
    if (t == 0) {
        unsigned v = atomicAdd(&g_done, 1u);
        is_last = (v == GRID - 1);
    }
    __syncthreads();
    if (!is_last) return;

    __threadfence();                     // acquire partials from other blocks
    if (t == 0) g_done = 0;              // reset for next graph replay

    // ---- phase 2: reduce CHUNKS partials per (b, d), write outputs ----
    __shared__ float tot[4][DIM];
    if (t < 128) {                       // b = t>>5, d = t&31
        const int bb = t >> 5;
        const int d  = t & 31;
        float acc = 0.0f;
        #pragma unroll
        for (int cc = 0; cc < CHUNKS; ++cc)
            acc += g_part[bb][cc][d];
        tot[bb][d] = acc * (1.0f / (float)NPTS);   // mean over nodes
    }
    __syncthreads();

    __shared__ float al[NW * DIM];
    if (t < NW * DIM) al[t] = alphas[t];
    __syncthreads();

    // 2560 outputs, 256 threads -> 10 per thread
    #pragma unroll
    for (int i = t; i < 4 * FOUT; i += 256) {
        const int bb  = i / FOUT;
        const int rem = i - bb * FOUT;
        const int w   = rem / (NCOLL * DIM);
        const int d   = rem & 31;
        out[i] = tot[bb][d] * al[w * DIM + d];
    }
}

extern "C" void kernel_launch(void* const* d_in, const int* in_sizes, int n_in,
                              void* d_out, int out_size)
{
    const float* pc     = (const float*)d_in[0];  // [4, 2048, 32] fp32
    // d_in[1] = sigma: output is invariant to the diffusion operator
    const float* alphas = (const float*)d_in[2];  // [4, 32] fp32
    float* out = (float*)d_out;                   // [4, 640] fp32

    hiponet_kernel<<<GRID, 256>>>(pc, alphas, out);
}

// round 3
// speedup vs baseline: 1.2353x; 1.0294x over previous
#include <cuda_runtime.h>

// HiPoNet collapse: P = 0.5*(Wm/colsum) + 0.5*I is column-stochastic, so
// 1^T P^t = 1^T and mean_n(P^t X) = mean_n(X) exactly. Output:
//   out[b, w*160 + k*32 + d] = mean_n(pc[b,n,d]) * alphas[w,d], k=0..4.
//
// R3: single launch, grid=16 (4 chunks x 4 batches), 512 thr/block.
// 8 independent LDG.128 per thread (MLP=8). 16-way arrival counter
// (atomic serialization ~440cyc vs ~3500cyc at grid=128). Last block
// reduces 4 partials per (b,d) and writes all 2560 outputs.

#define NPTS    2048
#define DIM     32
#define NW      4
#define NCOLL   5
#define FOUT    (NW * NCOLL * DIM)       // 640 per batch
#define CPB     4                        // chunks per batch
#define GRID    (4 * CPB)                // 16 blocks
#define ROWS    (NPTS / CPB)             // 512 rows per chunk
#define QPR     (DIM / 4)                // 8 float4 per row
#define BLK     512
#define RG      (BLK / QPR)              // 64 row groups
#define LPT     (ROWS / RG)              // 8 loads per thread

__device__ float        g_part[4][CPB][DIM];
__device__ unsigned int g_done;          // zero-init; self-resetting

__device__ __forceinline__ float4 f4add(float4 a, float4 b) {
    return make_float4(a.x + b.x, a.y + b.y, a.z + b.z, a.w + b.w);
}

__global__ __launch_bounds__(BLK, 1)
void hiponet_kernel(const float* __restrict__ pc,
                    const float* __restrict__ alphas,
                    float* __restrict__ out)
{
    const int b  = blockIdx.x >> 2;      // batch 0..3
    const int c  = blockIdx.x & 3;       // chunk 0..3
    const int t  = threadIdx.x;          // 0..511
    const int q  = t & (QPR - 1);        // float4 slot, 0..7
    const int rg = t >> 3;               // row group, 0..63

    const float4* __restrict__ base =
        (const float4*)(pc + ((size_t)b * NPTS + (size_t)c * ROWS) * DIM);

    // ---- phase 1: 8 independent LDG.128, pairwise-summed for ILP ----
    float4 v[LPT];
    #pragma unroll
    for (int k = 0; k < LPT; ++k)
        v[k] = base[(size_t)(rg + k * RG) * QPR + q];
    float4 s01 = f4add(v[0], v[1]);
    float4 s23 = f4add(v[2], v[3]);
    float4 s45 = f4add(v[4], v[5]);
    float4 s67 = f4add(v[6], v[7]);
    float4 s = f4add(f4add(s01, s23), f4add(s45, s67));

    __shared__ float4 sm[RG][QPR];
    sm[rg][q] = s;
    __syncthreads();

    #pragma unroll
    for (int st = RG / 2; st > 0; st >>= 1) {
        if (rg < st) sm[rg][q] = f4add(sm[rg][q], sm[rg + st][q]);
        __syncthreads();
    }

    if (t < QPR)
        ((float4*)g_part[b][c])[t] = sm[0][t];
    __threadfence();

    // ---- arrival count; last block finishes ----
    __shared__ bool is_last;
    if (t == 0) {
        unsigned v2 = atomicAdd(&g_done, 1u);
        is_last = (v2 == GRID - 1);
    }
    __syncthreads();
    if (!is_last) return;

    __threadfence();                     // acquire other blocks' partials
    if (t == 0) g_done = 0;              // reset for graph replay

    // ---- phase 2: reduce 4 partials per (b,d), write 2560 outputs ----
    __shared__ float tot[4][DIM];
    if (t < 128) {                       // bb = t>>5, d = t&31
        const int bb = t >> 5;
        const int d  = t & 31;
        float acc = (g_part[bb][0][d] + g_part[bb][1][d])
                  + (g_part[bb][2][d] + g_part[bb][3][d]);
        tot[bb][d] = acc * (1.0f / (float)NPTS);
    }
    __shared__ float al[NW * DIM];
    if (t >= 128 && t < 128 + NW * DIM) al[t - 128] = alphas[t - 128];
    __syncthreads();

    // 2560 outputs, 512 threads -> 5 each
    #pragma unroll
    for (int i = t; i < 4 * FOUT; i += BLK) {
        const int bb  = i / FOUT;
        const int rem = i - bb * FOUT;
        const int w   = rem / (NCOLL * DIM);
        const int d   = rem & 31;
        out[i] = tot[bb][d] * al[w * DIM + d];
    }
}

extern "C" void kernel_launch(void* const* d_in, const int* in_sizes, int n_in,
                              void* d_out, int out_size)
{
    const float* pc     = (const float*)d_in[0];  // [4, 2048, 32] fp32
    // d_in[1] = sigma: output is invariant to the diffusion operator
    const float* alphas = (const float*)d_in[2];  // [4, 32] fp32
    float* out = (float*)d_out;                   // [4, 640] fp32

    hiponet_kernel<<<GRID, BLK>>>(pc, alphas, out);
}